// round 2
// baseline (speedup 1.0000x reference)
#include <cuda_runtime.h>
#include <cuda_bf16.h>
#include <math.h>
#include <stdint.h>

// ---------------------------------------------------------------------------
// EnhancedRNN: emb -> GRU x2 -> LayerNorm -> tied head
// B=32, T=512, D=1024, L=2, VOCAB=256, fp32
//
// Strategy R1 (fp32 baseline, structured for later tensor-core upgrades):
//  1. G0 = E @ Wih0^T + bih0  (256x3072)  -> layer-0 xg becomes a gather
//  2. persistent grid-sync GRU recurrence, Whh slice resident in SMEM
//  3. xg1 = seq0 @ Wih1^T + bih1 (tiled fp32 GEMM)
//  4. second recurrence
//  5. LayerNorm
//  6. logits = hn @ E^T (tiled GEMM)
// ---------------------------------------------------------------------------

#define Bsz   32
#define Tlen  512
#define Dh    1024
#define G3    (3 * Dh)       // 3072
#define MROWS (Bsz * Tlen)   // 16384
#define NCTA  128            // recurrence CTAs (one wave, all resident)
#define HDC   8              // hidden units per CTA (1024/128)
#define RPC   24             // gate rows per CTA (3*HDC)
#define REDS  33             // padded reduce stride

// ------------------------- static device buffers ---------------------------
__device__ float g_G0[256 * G3];                     // 3 MB
__device__ float g_seq[(size_t)MROWS * Dh];          // 64 MB (layer outputs, reused)
__device__ float g_xg1[(size_t)MROWS * G3];          // 192 MB
__device__ float g_hn[(size_t)MROWS * Dh];           // 64 MB
__device__ float g_h[2][Bsz][Dh];                    // 256 KB recurrent state (double buffered)
__device__ int   g_xi[MROWS];
__device__ unsigned g_barc;                          // grid barrier arrive count
__device__ unsigned g_barg;                          // grid barrier generation

// ------------------------------ x decode -----------------------------------
// x may arrive as int64 (values < 256 => odd 32-bit words all zero) or int32.
__global__ void decode_x_kernel(const void* __restrict__ xin, int n, int* __restrict__ out) {
    const int* w = (const int*)xin;
    bool is64 = true;
    #pragma unroll
    for (int i = 1; i < 32; i += 2) if (w[i] != 0) is64 = false;
    int i = blockIdx.x * blockDim.x + threadIdx.x;
    if (i < n) out[i] = is64 ? (int)(((const long long*)xin)[i]) : w[i];
}

// --------------------------- tiled fp32 GEMM -------------------------------
// C[M][N] = A[M][K] @ B[N][K]^T (+ bias[N]).  M,N multiples of 128, K of 8.
__global__ __launch_bounds__(256) void gemm_abt_kernel(
    const float* __restrict__ A, const float* __restrict__ B,
    const float* __restrict__ bias, float* __restrict__ C,
    int M, int N, int K)
{
    __shared__ float As[8][128];
    __shared__ float Bs[8][128];
    const int tid = threadIdx.x;
    const int bm = blockIdx.y * 128;
    const int bn = blockIdx.x * 128;
    const int tx = tid & 15;         // n micro-tile
    const int ty = tid >> 4;         // m micro-tile

    const int arow = tid >> 1;       // 0..127
    const int acol = (tid & 1) * 4;  // 0 or 4

    const float* Aptr = A + (size_t)(bm + arow) * K + acol;
    const float* Bptr = B + (size_t)(bn + arow) * K + acol;

    float acc[8][8];
    #pragma unroll
    for (int i = 0; i < 8; i++)
        #pragma unroll
        for (int j = 0; j < 8; j++) acc[i][j] = 0.f;

    for (int kk = 0; kk < K; kk += 8) {
        float4 av = *(const float4*)(Aptr + kk);
        float4 bv = *(const float4*)(Bptr + kk);
        As[acol + 0][arow] = av.x; As[acol + 1][arow] = av.y;
        As[acol + 2][arow] = av.z; As[acol + 3][arow] = av.w;
        Bs[acol + 0][arow] = bv.x; Bs[acol + 1][arow] = bv.y;
        Bs[acol + 2][arow] = bv.z; Bs[acol + 3][arow] = bv.w;
        __syncthreads();
        #pragma unroll
        for (int k = 0; k < 8; k++) {
            float4 a0 = *(const float4*)&As[k][ty * 8];
            float4 a1 = *(const float4*)&As[k][ty * 8 + 4];
            float4 b0 = *(const float4*)&Bs[k][tx * 8];
            float4 b1 = *(const float4*)&Bs[k][tx * 8 + 4];
            float am[8] = {a0.x, a0.y, a0.z, a0.w, a1.x, a1.y, a1.z, a1.w};
            float bnv[8] = {b0.x, b0.y, b0.z, b0.w, b1.x, b1.y, b1.z, b1.w};
            #pragma unroll
            for (int i = 0; i < 8; i++)
                #pragma unroll
                for (int j = 0; j < 8; j++)
                    acc[i][j] = fmaf(am[i], bnv[j], acc[i][j]);
        }
        __syncthreads();
    }

    #pragma unroll
    for (int i = 0; i < 8; i++) {
        const int row = bm + ty * 8 + i;
        float* crow = C + (size_t)row * N + bn + tx * 8;
        #pragma unroll
        for (int j = 0; j < 8; j++) {
            float b = bias ? bias[bn + tx * 8 + j] : 0.f;
            crow[j] = acc[i][j] + b;
        }
    }
}

// --------------------------- grid barrier ----------------------------------
__device__ __forceinline__ void grid_barrier(unsigned nb) {
    __syncthreads();
    if (threadIdx.x == 0) {
        __threadfence();
        unsigned g = *((volatile unsigned*)&g_barg);
        if (atomicAdd(&g_barc, 1u) == nb - 1u) {
            g_barc = 0u;
            __threadfence();
            atomicAdd(&g_barg, 1u);
        } else {
            while (*((volatile unsigned*)&g_barg) == g) { }
        }
    }
    __syncthreads();
}

// --------------------------- GRU recurrence --------------------------------
// Persistent: CTA c owns hidden units d in [c*8, c*8+8) -> 24 Whh rows in SMEM.
// Per step: hg = Whh_slice @ h (8-warp k-split), reduce, gates, write h_new.
template<bool L0>
__global__ __launch_bounds__(256, 1) void gru_kernel(
    const float* __restrict__ Whh, const float* __restrict__ bhh,
    const float* __restrict__ xg,            // L0: G0[256][3072], L1: xg1[16384][3072]
    const int* __restrict__ xidx,            // tokens [32][512] (L0 only)
    float* __restrict__ seq_out)             // [32][512][1024]
{
    extern __shared__ float sm[];
    float*  Ws  = sm;                         // [24][1024]
    float*  red = sm + RPC * Dh;              // [8][24][33]
    const int c   = blockIdx.x;
    const int tid = threadIdx.x;
    const int w    = tid >> 5;                // warp id = k-slice
    const int lane = tid & 31;                // = batch b
    const int d_loc  = tid >> 5;              // epilogue: hidden unit within slice
    const int b      = tid & 31;
    const int d_glob = c * HDC + d_loc;

    // load Whh slice rows {d, 1024+d, 2048+d : d in slice} -> Ws[lr][1024]
    for (int i = tid; i < RPC * (Dh / 4); i += 256) {
        int lr = i / (Dh / 4);
        int kc = i % (Dh / 4);
        int g  = lr / HDC, j = lr % HDC;
        int grow = g * Dh + c * HDC + j;
        ((float4*)Ws)[lr * (Dh / 4) + kc] =
            ((const float4*)(Whh + (size_t)grow * Dh))[kc];
    }
    // biases for this thread's hidden unit
    const float brr = bhh[d_glob];
    const float bzz = bhh[Dh + d_glob];
    const float bnn = bhh[2 * Dh + d_glob];
    // zero h buffer 0 (each CTA covers its 8 d x 32 b)
    __stcg(&g_h[0][b][d_glob], 0.f);

    grid_barrier(NCTA);

    const float4* wsp = (const float4*)Ws;   // [24][256]

    for (int t = 0; t < Tlen; t++) {
        const int cur = t & 1, nxt = (t + 1) & 1;
        // ---- GEMM phase: warp w covers k in [w*128, w*128+128) ----
        float acc[RPC];
        #pragma unroll
        for (int r = 0; r < RPC; r++) acc[r] = 0.f;

        const float4* hp4 = ((const float4*)&g_h[cur][0][0]) + lane * (Dh / 4) + w * 32;
        float4 h0 = __ldcg(hp4 + 0);
        float4 h1 = __ldcg(hp4 + 1);
        float4 h2 = __ldcg(hp4 + 2);
        float4 h3 = __ldcg(hp4 + 3);
        #pragma unroll 2
        for (int kk = 0; kk < 32; kk++) {
            float4 hv = h0; h0 = h1; h1 = h2; h2 = h3;
            if (kk + 4 < 32) h3 = __ldcg(hp4 + kk + 4);
            const float4* wr = wsp + w * 32 + kk;
            #pragma unroll
            for (int r = 0; r < RPC; r++) {
                float4 wv = wr[r * (Dh / 4)];
                acc[r] = fmaf(wv.x, hv.x,
                         fmaf(wv.y, hv.y,
                         fmaf(wv.z, hv.z,
                         fmaf(wv.w, hv.w, acc[r]))));
            }
        }
        #pragma unroll
        for (int r = 0; r < RPC; r++) red[(w * RPC + r) * REDS + lane] = acc[r];
        __syncthreads();

        // ---- epilogue: reduce 8 warps, gates, state update ----
        float hr = brr, hz = bzz, hn = bnn;
        #pragma unroll
        for (int ww = 0; ww < 8; ww++) {
            hr += red[(ww * RPC +      d_loc) * REDS + b];
            hz += red[(ww * RPC +  8 + d_loc) * REDS + b];
            hn += red[(ww * RPC + 16 + d_loc) * REDS + b];
        }
        float xr, xz, xn;
        if (L0) {
            int ix = xidx[b * Tlen + t];
            const float* g = xg + (size_t)ix * G3 + d_glob;
            xr = g[0]; xz = g[Dh]; xn = g[2 * Dh];
        } else {
            const float* g = xg + ((size_t)b * Tlen + t) * G3 + d_glob;
            xr = g[0]; xz = g[Dh]; xn = g[2 * Dh];
        }
        float r = 1.f / (1.f + __expf(-(xr + hr)));
        float z = 1.f / (1.f + __expf(-(xz + hz)));
        float n = tanhf(xn + r * hn);
        float hp = __ldcg(&g_h[cur][b][d_glob]);
        float hnew = (1.f - z) * n + z * hp;
        __stcg(&g_h[nxt][b][d_glob], hnew);
        seq_out[((size_t)b * Tlen + t) * Dh + d_glob] = hnew;

        grid_barrier(NCTA);   // publishes h_new; also guards red reuse
    }
}

// ------------------------------ LayerNorm ----------------------------------
__global__ __launch_bounds__(256) void ln_kernel(
    const float* __restrict__ in, const float* __restrict__ gamma,
    const float* __restrict__ beta, float* __restrict__ out)
{
    __shared__ float ssum[8], ssq[8], smu, srs;
    const int row = blockIdx.x;
    const int tid = threadIdx.x;
    const float4* ip = (const float4*)(in + (size_t)row * Dh);
    float4 v = ip[tid];
    float s = v.x + v.y + v.z + v.w;
    float q = v.x * v.x + v.y * v.y + v.z * v.z + v.w * v.w;
    #pragma unroll
    for (int o = 16; o > 0; o >>= 1) {
        s += __shfl_xor_sync(0xffffffffu, s, o);
        q += __shfl_xor_sync(0xffffffffu, q, o);
    }
    if ((tid & 31) == 0) { ssum[tid >> 5] = s; ssq[tid >> 5] = q; }
    __syncthreads();
    if (tid == 0) {
        float ts = 0.f, tq = 0.f;
        #pragma unroll
        for (int i = 0; i < 8; i++) { ts += ssum[i]; tq += ssq[i]; }
        float mu = ts / (float)Dh;
        float var = tq / (float)Dh - mu * mu;
        smu = mu;
        srs = rsqrtf(var + 1e-5f);
    }
    __syncthreads();
    const float mu = smu, rs = srs;
    float4 g = ((const float4*)gamma)[tid];
    float4 be = ((const float4*)beta)[tid];
    float4 o;
    o.x = (v.x - mu) * rs * g.x + be.x;
    o.y = (v.y - mu) * rs * g.y + be.y;
    o.z = (v.z - mu) * rs * g.z + be.z;
    o.w = (v.w - mu) * rs * g.w + be.w;
    ((float4*)(out + (size_t)row * Dh))[tid] = o;
}

// ------------------------------ launch -------------------------------------
extern "C" void kernel_launch(void* const* d_in, const int* in_sizes, int n_in,
                              void* d_out, int out_size)
{
    (void)in_sizes; (void)n_in; (void)out_size;
    const void*  x     = d_in[0];
    const float* E     = (const float*)d_in[1];
    const float* Wih   = (const float*)d_in[2];   // [2][3072][1024]
    const float* Whh   = (const float*)d_in[3];   // [2][3072][1024]
    const float* bih   = (const float*)d_in[4];   // [2][3072]
    const float* bhh   = (const float*)d_in[5];   // [2][3072]
    const float* gamma = (const float*)d_in[6];
    const float* beta  = (const float*)d_in[7];
    float* out = (float*)d_out;

    float *pG0, *pseq, *pxg1, *phn;
    int* pxi;
    cudaGetSymbolAddress((void**)&pG0,  g_G0);
    cudaGetSymbolAddress((void**)&pseq, g_seq);
    cudaGetSymbolAddress((void**)&pxg1, g_xg1);
    cudaGetSymbolAddress((void**)&phn,  g_hn);
    cudaGetSymbolAddress((void**)&pxi,  g_xi);

    const int gru_smem = (RPC * Dh + 8 * RPC * REDS) * (int)sizeof(float); // ~124 KB
    cudaFuncSetAttribute(gru_kernel<true>,  cudaFuncAttributeMaxDynamicSharedMemorySize, gru_smem);
    cudaFuncSetAttribute(gru_kernel<false>, cudaFuncAttributeMaxDynamicSharedMemorySize, gru_smem);

    // 1. decode tokens
    decode_x_kernel<<<32, 512>>>(x, MROWS, pxi);
    // 2. G0 = E @ Wih0^T + bih0   [256 x 3072]
    gemm_abt_kernel<<<dim3(G3 / 128, 256 / 128), 256>>>(E, Wih, bih, pG0, 256, G3, Dh);
    // 3. layer-0 recurrence (xg via G0 gather)
    gru_kernel<true><<<NCTA, 256, gru_smem>>>(Whh, bhh, pG0, pxi, pseq);
    // 4. xg1 = seq0 @ Wih1^T + bih1   [16384 x 3072]
    gemm_abt_kernel<<<dim3(G3 / 128, MROWS / 128), 256>>>(
        pseq, Wih + (size_t)G3 * Dh, bih + G3, pxg1, MROWS, G3, Dh);
    // 5. layer-1 recurrence (overwrites g_seq)
    gru_kernel<false><<<NCTA, 256, gru_smem>>>(
        Whh + (size_t)G3 * Dh, bhh + G3, pxg1, nullptr, pseq);
    // 6. LayerNorm
    ln_kernel<<<MROWS, 256>>>(pseq, gamma, beta, phn);
    // 7. logits = hn @ E^T   [16384 x 256] -> d_out
    gemm_abt_kernel<<<dim3(256 / 128, MROWS / 128), 256>>>(
        phn, E, nullptr, out, MROWS, 256, Dh);
}